// round 15
// baseline (speedup 1.0000x reference)
#include <cuda_runtime.h>
#include <math.h>
#include <stdint.h>

// Problem constants (fixed by the dataset)
#define BATCH 4
#define TSEQ  2048
#define CDIM  1024
#define NH    16
#define DH    64
#define BT    (BATCH * TSEQ)   // 8192 rows
#define BH    (BATCH * NH)     // 64 (batch*heads)

// ---------------------------------------------------------------------------
// Scratch (device globals; no allocation allowed in kernel_launch)
// ---------------------------------------------------------------------------
__device__ float g_Qh[(size_t)BH * TSEQ * DH];       // [bh][t][d], rope'd, *0.125
__device__ float g_Kh[(size_t)BH * TSEQ * DH];       // [bh][t][d], rope'd
__device__ float g_Vh[(size_t)BH * TSEQ * DH];       // [bh][t][d]
__device__ float g_Oh[(size_t)BT * CDIM];            // attention out, [b*T+t][h*64+d]
__device__ float g_cosT[TSEQ * (DH / 2)];            // rope tables
__device__ float g_sinT[TSEQ * (DH / 2)];

// ---------------------------------------------------------------------------
// Helpers
// ---------------------------------------------------------------------------
// pack two fp32 into fp16x2: lo = first arg, hi = second arg
__device__ __forceinline__ uint32_t f16x2(float lo, float hi) {
    uint32_t r;
    asm("cvt.rn.f16x2.f32 %0, %1, %2;" : "=r"(r) : "f"(hi), "f"(lo));
    return r;
}

#define MMA_F16(d, a0, a1, a2, a3, b0, b1)                                   \
    asm volatile(                                                            \
        "mma.sync.aligned.m16n8k16.row.col.f32.f16.f16.f32 "                 \
        "{%0,%1,%2,%3}, {%4,%5,%6,%7}, {%8,%9}, {%0,%1,%2,%3};"              \
        : "+f"(d[0]), "+f"(d[1]), "+f"(d[2]), "+f"(d[3])                     \
        : "r"(a0), "r"(a1), "r"(a2), "r"(a3), "r"(b0), "r"(b1))

#define CP_ASYNC16(dst_u32, src_ptr)                                         \
    asm volatile("cp.async.cg.shared.global [%0], [%1], 16;"                 \
                 :: "r"(dst_u32), "l"(src_ptr))
#define CP_COMMIT() asm volatile("cp.async.commit_group;")
#define CP_WAIT(n)  asm volatile("cp.async.wait_group %0;" :: "n"(n))

__device__ __forceinline__ uint32_t smem_u32(const void* p) {
    uint32_t a;
    asm("{ .reg .u64 t; cvta.to.shared.u64 t, %1; cvt.u32.u64 %0, t; }"
        : "=r"(a) : "l"(p));
    return a;
}

// ---------------------------------------------------------------------------
// RoPE tables
// ---------------------------------------------------------------------------
__global__ void build_tables_kernel() {
    int idx = blockIdx.x * blockDim.x + threadIdx.x;     // t*32 + i
    if (idx >= TSEQ * (DH / 2)) return;
    int t = idx >> 5;
    int i = idx & 31;
    float theta_f = (float)pow(10000.0, -(double)(2 * i) / (double)DH);
    float angle_f = (float)t * theta_f;
    g_cosT[idx] = (float)cos((double)angle_f);
    g_sinT[idx] = (float)sin((double)angle_f);
}

// ---------------------------------------------------------------------------
// NT GEMM via fp16 mma.sync (fp32 accum): C[M,N] = A[M,K] * B[N,K]^T.
// CTA tile 128x128, BK=16, 256 threads = 8 warps (4x2), warp tile 32x64.
// cp.async 3-stage pipeline of raw fp32; fragment build = float2 (LDS.64)
// + one cvt.rn.f16x2 per packed register.
// MODE 0: plain fp32 C write.  MODE 1: fused RoPE + head split (QKV).
// ---------------------------------------------------------------------------
#define GP 20            // smem row stride (fp32 words); 80B, 16B-aligned
#define NSTAGE 3
#define STAGE_U (2 * 128 * GP)
#define GEMM_SMEM (NSTAGE * STAGE_U * (int)sizeof(uint32_t))   // 61440 B

template <int MODE>
__global__ __launch_bounds__(256, 2) void gemm_nt_f16(
    const float* __restrict__ A, const float* __restrict__ B,
    float* __restrict__ C, int M, int N, int K)
{
    extern __shared__ __align__(16) float gsm[];

    const int tid  = threadIdx.x;
    const int lane = tid & 31;
    const int w    = tid >> 5;
    const int lr   = lane >> 2;
    const int lc   = lane & 3;
    const int wm   = (w >> 1) * 32;
    const int wn   = (w & 1) * 64;
    const int bm   = blockIdx.y * 128;
    const int bn   = blockIdx.x * 128;

    const uint32_t sbase = smem_u32(gsm);

    float acc[2][8][4] = {};

    const float* Abase = A + (size_t)bm * K;
    const float* Bbase = B + (size_t)bn * K;

    auto issue_stage = [&](int it, int stage) {
        uint32_t sA = sbase + stage * STAGE_U * 4;
        uint32_t sB = sA + 128 * GP * 4;
        int koff = it * 16;
#pragma unroll
        for (int i = 0; i < 2; i++) {
            int id = tid + i * 256;
            int r = id >> 2;
            int c = id & 3;
            CP_ASYNC16(sA + (r * GP + c * 4) * 4, Abase + (size_t)r * K + koff + c * 4);
            CP_ASYNC16(sB + (r * GP + c * 4) * 4, Bbase + (size_t)r * K + koff + c * 4);
        }
    };

    const int NIT = K / 16;
#pragma unroll
    for (int s = 0; s < NSTAGE - 1; s++) {
        issue_stage(s, s);
        CP_COMMIT();
    }

    for (int it = 0; it < NIT; it++) {
        CP_WAIT(NSTAGE - 2);
        __syncthreads();

        if (it + NSTAGE - 1 < NIT) {
            issue_stage(it + NSTAGE - 1, (it + NSTAGE - 1) % NSTAGE);
            CP_COMMIT();
        }

        const float* Ac = gsm + (it % NSTAGE) * STAGE_U;
        const float* Bc = Ac + 128 * GP;

        uint32_t a[2][4];
#pragma unroll
        for (int mt = 0; mt < 2; mt++) {
            const float* p0 = Ac + (wm + mt * 16 + lr) * GP;
            const float* p1 = p0 + 8 * GP;
            float2 u0 = *(const float2*)&p0[2 * lc];
            float2 u1 = *(const float2*)&p1[2 * lc];
            float2 u2 = *(const float2*)&p0[2 * lc + 8];
            float2 u3 = *(const float2*)&p1[2 * lc + 8];
            a[mt][0] = f16x2(u0.x, u0.y);
            a[mt][1] = f16x2(u1.x, u1.y);
            a[mt][2] = f16x2(u2.x, u2.y);
            a[mt][3] = f16x2(u3.x, u3.y);
        }
        uint32_t b[8][2];
#pragma unroll
        for (int nt = 0; nt < 8; nt++) {
            const float* pn = Bc + (wn + nt * 8 + lr) * GP;
            float2 v0 = *(const float2*)&pn[2 * lc];
            float2 v1 = *(const float2*)&pn[2 * lc + 8];
            b[nt][0] = f16x2(v0.x, v0.y);
            b[nt][1] = f16x2(v1.x, v1.y);
        }
#pragma unroll
        for (int mt = 0; mt < 2; mt++)
#pragma unroll
            for (int nt = 0; nt < 8; nt++)
                MMA_F16(acc[mt][nt], a[mt][0], a[mt][1], a[mt][2], a[mt][3],
                        b[nt][0], b[nt][1]);

        __syncthreads();
    }

    // ---- epilogue ----
    if (MODE == 0) {
#pragma unroll
        for (int mt = 0; mt < 2; mt++) {
#pragma unroll
            for (int nt = 0; nt < 8; nt++) {
                size_t r = (size_t)(bm + wm + mt * 16 + lr);
                int col = bn + wn + nt * 8 + 2 * lc;
                *(float2*)&C[r * N + col] =
                    make_float2(acc[mt][nt][0], acc[mt][nt][1]);
                *(float2*)&C[(r + 8) * N + col] =
                    make_float2(acc[mt][nt][2], acc[mt][nt][3]);
            }
        }
    } else {
        // fused RoPE + head split. col pair (2lc, 2lc+1) == rope pair (j, j+1).
#pragma unroll
        for (int mt = 0; mt < 2; mt++) {
#pragma unroll
            for (int nt = 0; nt < 8; nt++) {
                int col    = bn + wn + nt * 8 + 2 * lc;
                int s      = col >> 10;              // 0=q 1=k 2=v
                int within = col & (CDIM - 1);
                int hh     = within >> 6;
                int j      = within & (DH - 1);      // even
#pragma unroll
                for (int h2 = 0; h2 < 2; h2++) {
                    int row = bm + wm + mt * 16 + lr + 8 * h2;
                    int t   = row & (TSEQ - 1);
                    int b_  = row >> 11;
                    float e0 = acc[mt][nt][2 * h2];
                    float e1 = acc[mt][nt][2 * h2 + 1];
                    size_t dst = (((size_t)(b_ * NH + hh) * TSEQ) + t) * DH + j;
                    if (s == 2) {
                        *(float2*)(g_Vh + dst) = make_float2(e0, e1);
                    } else {
                        float c  = g_cosT[t * 32 + (j >> 1)];
                        float sn = g_sinT[t * 32 + (j >> 1)];
                        float o0 = e0 * c - e1 * sn;
                        float o1 = e1 * c + e0 * sn;
                        if (s == 0) {
                            o0 *= 0.125f; o1 *= 0.125f;   // 1/sqrt(d_head) into Q
                            *(float2*)(g_Qh + dst) = make_float2(o0, o1);
                        } else {
                            *(float2*)(g_Kh + dst) = make_float2(o0, o1);
                        }
                    }
                }
            }
        }
    }
}

// ---------------------------------------------------------------------------
// Flash attention, fp16 mma (fp32 accum). Q tile 128 rows (8 warps x m16),
// K tile 64.
// Pair-interleaved fp16 smem layouts (per 16-element group along the mma
// k-dim, pair slots stored as p0,p4,p1,p5,p2,p6,p3,p7) so every B/A fragment
// pair is one LDS.64:
//   Ks16 [key][d-groups]     QK B operand
//   Vt16 [d][key-groups]     PV B operand (transposed fp16, built in staging)
//   Ps16 [q][key-groups]     PV A operand
// All strides 144B (conflict-free for the fragment access pattern).
// ---------------------------------------------------------------------------
#define KST 144
#define VST 144
#define PST 144
#define ATTN_SMEM (64 * KST + 64 * VST + 128 * PST)   // 36864 B

__global__ __launch_bounds__(256) void attn_f16_kernel() {
    extern __shared__ __align__(16) char sm[];
    char* Ks16 = sm;                         // [64 key][KST]
    char* Vt16 = sm + 64 * KST;              // [64 d][VST]
    char* Ps16 = sm + 64 * KST + 64 * VST;   // [128 q][PST]

    const int tid  = threadIdx.x;
    const int lane = tid & 31;
    const int w    = tid >> 5;          // warp 0..7 -> q rows w*16..w*16+15
    const int lr   = lane >> 2;
    const int lc   = lane & 3;
    const int iq   = blockIdx.x;        // q tile (128 rows)
    const int bh   = blockIdx.y;

    const float* Qg = g_Qh + ((size_t)bh * TSEQ + iq * 128) * DH;
    const float* Kg = g_Kh + (size_t)bh * TSEQ * DH;
    const float* Vg = g_Vh + (size_t)bh * TSEQ * DH;

    // Q fragments (fp16 packed) in registers, reused for all key tiles.
    uint32_t qf[4][4];
    {
        const float* q0 = Qg + (w * 16 + lr) * DH;
        const float* q1 = q0 + 8 * DH;
#pragma unroll
        for (int kk = 0; kk < 4; kk++) {
            int k = kk * 16 + 2 * lc;
            float2 u0 = *(const float2*)&q0[k];
            float2 u1 = *(const float2*)&q1[k];
            float2 u2 = *(const float2*)&q0[k + 8];
            float2 u3 = *(const float2*)&q1[k + 8];
            qf[kk][0] = f16x2(u0.x, u0.y);
            qf[kk][1] = f16x2(u1.x, u1.y);
            qf[kk][2] = f16x2(u2.x, u2.y);
            qf[kk][3] = f16x2(u3.x, u3.y);
        }
    }

    float oacc[8][4] = {};
    float mrow[2] = {-INFINITY, -INFINITY};
    float lrow[2] = {0.f, 0.f};

    const int NJ = 2 * iq + 2;          // key tiles covering keys <= max row
    for (int j = 0; j < NJ; j++) {
        __syncthreads();                // prior tile's smem reads complete
        const float* Kt = Kg + (size_t)(j * 64) * DH;
        const float* Vt = Vg + (size_t)(j * 64) * DH;

        // ---- stage K: one (row, 16-d group) per thread, pair-interleaved ----
        {
            int r = tid >> 2;
            int g = tid & 3;
            const float* src = Kt + r * DH + g * 16;
            float4 u0 = *(const float4*)(src);
            float4 u1 = *(const float4*)(src + 4);
            float4 u2 = *(const float4*)(src + 8);
            float4 u3 = *(const float4*)(src + 12);
            char* dst = Ks16 + r * KST + g * 32;
            *(uint4*)dst = make_uint4(
                f16x2(u0.x, u0.y), f16x2(u2.x, u2.y),
                f16x2(u0.z, u0.w), f16x2(u2.z, u2.w));
            *(uint4*)(dst + 16) = make_uint4(
                f16x2(u1.x, u1.y), f16x2(u3.x, u3.y),
                f16x2(u1.z, u1.w), f16x2(u3.z, u3.w));
        }
        // ---- stage V transposed fp16: 8 (d, key-pair) cells per thread ----
#pragma unroll
        for (int i = 0; i < 8; i++) {
            int id = tid + i * 256;          // 0..2047
            int d  = id & 63;
            int p  = id >> 6;                // key pair index 0..31
            int g  = p >> 3;
            int i8 = p & 7;
            int slot = 2 * (i8 & 3) + (i8 >> 2);
            uint32_t pair = f16x2(Vt[(2 * p) * DH + d], Vt[(2 * p + 1) * DH + d]);
            *(uint32_t*)(Vt16 + d * VST + g * 32 + slot * 4) = pair;
        }
        __syncthreads();

        // ---- S = Q K^T  (m16 x n64, 4 x k16) ----
        float s[8][4] = {};
#pragma unroll
        for (int kk = 0; kk < 4; kk++) {
#pragma unroll
            for (int nt = 0; nt < 8; nt++) {
                uint2 b2 = *(const uint2*)(Ks16 + (nt * 8 + lr) * KST + kk * 32 + lc * 8);
                MMA_F16(s[nt], qf[kk][0], qf[kk][1], qf[kk][2], qf[kk][3],
                        b2.x, b2.y);
            }
        }

        // ---- causal mask (only last two tiles can be partial) ----
        if (j >= 2 * iq) {
            int rbase = iq * 128 + w * 16 + lr;
            int cbase = j * 64 + 2 * lc;
#pragma unroll
            for (int nt = 0; nt < 8; nt++) {
#pragma unroll
                for (int e = 0; e < 4; e++) {
                    int rl = rbase + (e >> 1) * 8;
                    int cl = cbase + nt * 8 + (e & 1);
                    if (cl > rl) s[nt][e] = -INFINITY;
                }
            }
        }

        // ---- online softmax (per row half) + P store (interleaved fp16) ----
#pragma unroll
        for (int h = 0; h < 2; h++) {
            float mx = -INFINITY;
#pragma unroll
            for (int nt = 0; nt < 8; nt++)
                mx = fmaxf(mx, fmaxf(s[nt][2 * h], s[nt][2 * h + 1]));
            mx = fmaxf(mx, __shfl_xor_sync(0xffffffffu, mx, 1));
            mx = fmaxf(mx, __shfl_xor_sync(0xffffffffu, mx, 2));
            float mnew = fmaxf(mrow[h], mx);
            float alpha = __expf(mrow[h] - mnew);
            float rs = 0.f;
#pragma unroll
            for (int nt = 0; nt < 8; nt++) {
                float p0 = __expf(s[nt][2 * h] - mnew);
                float p1 = __expf(s[nt][2 * h + 1] - mnew);
                s[nt][2 * h] = p0;
                s[nt][2 * h + 1] = p1;
                rs += p0 + p1;
            }
            rs += __shfl_xor_sync(0xffffffffu, rs, 1);
            rs += __shfl_xor_sync(0xffffffffu, rs, 2);
            lrow[h] = lrow[h] * alpha + rs;
            mrow[h] = mnew;
#pragma unroll
            for (int nt = 0; nt < 8; nt++) {
                oacc[nt][2 * h] *= alpha;
                oacc[nt][2 * h + 1] *= alpha;
            }
            int pr = w * 16 + lr + 8 * h;
#pragma unroll
            for (int nt = 0; nt < 8; nt++) {
                // key pair index within its 16-key group: i8 = (nt&1)*4 + lc
                int slot = 2 * lc + (nt & 1);
                *(uint32_t*)(Ps16 + pr * PST + (nt >> 1) * 32 + slot * 4) =
                    f16x2(s[nt][2 * h], s[nt][2 * h + 1]);
            }
        }
        __syncwarp();   // this warp's Ps rows only

        // ---- O += P * V  (m16 x n64, 4 x k16 over keys) ----
#pragma unroll
        for (int kk = 0; kk < 4; kk++) {
            int m = w * 16 + lr;
            uint2 pa = *(const uint2*)(Ps16 + m * PST + kk * 32 + lc * 8);
            uint2 pb = *(const uint2*)(Ps16 + (m + 8) * PST + kk * 32 + lc * 8);
            uint32_t a0 = pa.x, a2 = pa.y, a1 = pb.x, a3 = pb.y;
#pragma unroll
            for (int nt = 0; nt < 8; nt++) {
                uint2 vb = *(const uint2*)(Vt16 + (nt * 8 + lr) * VST + kk * 32 + lc * 8);
                MMA_F16(oacc[nt], a0, a1, a2, a3, vb.x, vb.y);
            }
        }
    }

    // ---- epilogue: normalize, write [b*T+t][h*64+d] ----
    const int bb = bh >> 4;
    const int hh = bh & 15;
#pragma unroll
    for (int h = 0; h < 2; h++) {
        float inv = 1.f / lrow[h];
        size_t row = (size_t)bb * TSEQ + (size_t)iq * 128 + w * 16 + lr + 8 * h;
        float* dst = g_Oh + row * CDIM + hh * DH;
#pragma unroll
        for (int nt = 0; nt < 8; nt++) {
            int col = nt * 8 + 2 * lc;
            *(float2*)&dst[col] = make_float2(oacc[nt][2 * h] * inv,
                                              oacc[nt][2 * h + 1] * inv);
        }
    }
}

// ---------------------------------------------------------------------------
// Launch
// ---------------------------------------------------------------------------
extern "C" void kernel_launch(void* const* d_in, const int* in_sizes, int n_in,
                              void* d_out, int out_size)
{
    const float* x    = (const float*)d_in[0];
    const float* Wqkv = (const float*)d_in[2];
    const float* Wout = (const float*)d_in[3];
    for (int i = 0; i < n_in; i++) {
        if (in_sizes[i] == BT * CDIM)            x    = (const float*)d_in[i];
        else if (in_sizes[i] == 3 * CDIM * CDIM) Wqkv = (const float*)d_in[i];
        else if (in_sizes[i] == CDIM * CDIM)     Wout = (const float*)d_in[i];
    }
    float* out = (float*)d_out;

    void* p_oh;
    cudaGetSymbolAddress(&p_oh, g_Oh);

    cudaFuncSetAttribute(attn_f16_kernel,
                         cudaFuncAttributeMaxDynamicSharedMemorySize, ATTN_SMEM);
    cudaFuncSetAttribute(gemm_nt_f16<0>,
                         cudaFuncAttributeMaxDynamicSharedMemorySize, GEMM_SMEM);
    cudaFuncSetAttribute(gemm_nt_f16<1>,
                         cudaFuncAttributeMaxDynamicSharedMemorySize, GEMM_SMEM);

    // 1. RoPE tables
    build_tables_kernel<<<(TSEQ * 32 + 255) / 256, 256>>>();

    // 2. QKV = x @ Wqkv^T with fused RoPE + head split (writes g_Qh/g_Kh/g_Vh)
    gemm_nt_f16<1><<<dim3(3 * CDIM / 128, BT / 128), 256, GEMM_SMEM>>>(
        x, Wqkv, nullptr, BT, 3 * CDIM, CDIM);

    // 3. Flash attention (causal, fp16 mma, 128-row Q tiles)
    attn_f16_kernel<<<dim3(TSEQ / 128, BH), 256, ATTN_SMEM>>>();

    // 4. out = attn_out @ Wout^T
    gemm_nt_f16<0><<<dim3(CDIM / 128, BT / 128), 256, GEMM_SMEM>>>(
        (const float*)p_oh, Wout, out, BT, CDIM, CDIM);
}

// round 16
// speedup vs baseline: 1.6392x; 1.6392x over previous
#include <cuda_runtime.h>
#include <math.h>
#include <stdint.h>

// Problem constants (fixed by the dataset)
#define BATCH 4
#define TSEQ  2048
#define CDIM  1024
#define NH    16
#define DH    64
#define BT    (BATCH * TSEQ)   // 8192 rows
#define BH    (BATCH * NH)     // 64 (batch*heads)

// ---------------------------------------------------------------------------
// Scratch (device globals; no allocation allowed in kernel_launch)
// fp16 tensors are stored pair-interleaved within each 16-element k-group:
// word w of a group holds pair p(w) = (w>>1) + (w&1)*4  (elements 2p, 2p+1),
// so an mma operand pair (b0,b1)/(a0,a2) is one aligned uint2 (LDS.64/LDG.64).
// ---------------------------------------------------------------------------
__device__ uint32_t g_x16[(size_t)BT * CDIM / 2];        // x, fp16i
__device__ uint32_t g_Wqkv16[(size_t)3 * CDIM * CDIM / 2];
__device__ uint32_t g_Wout16[(size_t)CDIM * CDIM / 2];
__device__ uint32_t g_Qh16[(size_t)BH * TSEQ * DH / 2];  // rope'd, *0.125, fp16i
__device__ uint32_t g_Kh16[(size_t)BH * TSEQ * DH / 2];  // rope'd, fp16i
__device__ float    g_Vh[(size_t)BH * TSEQ * DH];        // fp32 (R14 V path)
__device__ uint32_t g_Oh16[(size_t)BT * CDIM / 2];       // attention out, fp16i
__device__ float    g_cosT[TSEQ * (DH / 2)];
__device__ float    g_sinT[TSEQ * (DH / 2)];

// ---------------------------------------------------------------------------
// Helpers
// ---------------------------------------------------------------------------
__device__ __forceinline__ uint32_t f16x2(float lo, float hi) {
    uint32_t r;
    asm("cvt.rn.f16x2.f32 %0, %1, %2;" : "=r"(r) : "f"(hi), "f"(lo));
    return r;
}

#define MMA_F16(d, a0, a1, a2, a3, b0, b1)                                   \
    asm volatile(                                                            \
        "mma.sync.aligned.m16n8k16.row.col.f32.f16.f16.f32 "                 \
        "{%0,%1,%2,%3}, {%4,%5,%6,%7}, {%8,%9}, {%0,%1,%2,%3};"              \
        : "+f"(d[0]), "+f"(d[1]), "+f"(d[2]), "+f"(d[3])                     \
        : "r"(a0), "r"(a1), "r"(a2), "r"(a3), "r"(b0), "r"(b1))

#define CP_ASYNC16(dst_u32, src_ptr)                                         \
    asm volatile("cp.async.cg.shared.global [%0], [%1], 16;"                 \
                 :: "r"(dst_u32), "l"(src_ptr))
#define CP_COMMIT() asm volatile("cp.async.commit_group;")
#define CP_WAIT(n)  asm volatile("cp.async.wait_group %0;" :: "n"(n))

__device__ __forceinline__ uint32_t smem_u32(const void* p) {
    uint32_t a;
    asm("{ .reg .u64 t; cvta.to.shared.u64 t, %1; cvt.u32.u64 %0, t; }"
        : "=r"(a) : "l"(p));
    return a;
}

// ---------------------------------------------------------------------------
// RoPE tables
// ---------------------------------------------------------------------------
__global__ void build_tables_kernel() {
    int idx = blockIdx.x * blockDim.x + threadIdx.x;     // t*32 + i
    if (idx >= TSEQ * (DH / 2)) return;
    int t = idx >> 5;
    int i = idx & 31;
    float theta_f = (float)pow(10000.0, -(double)(2 * i) / (double)DH);
    float angle_f = (float)t * theta_f;
    g_cosT[idx] = (float)cos((double)angle_f);
    g_sinT[idx] = (float)sin((double)angle_f);
}

// ---------------------------------------------------------------------------
// fp32 -> pair-interleaved fp16 conversion. One thread = one 16-elem group.
// ---------------------------------------------------------------------------
__global__ __launch_bounds__(256) void convert_f16i_kernel(
    const float* __restrict__ src, uint32_t* __restrict__ dst, int ngroups)
{
    int g = blockIdx.x * blockDim.x + threadIdx.x;
    if (g >= ngroups) return;
    const float* s = src + (size_t)g * 16;
    float4 u0 = *(const float4*)(s);
    float4 u1 = *(const float4*)(s + 4);
    float4 u2 = *(const float4*)(s + 8);
    float4 u3 = *(const float4*)(s + 12);
    uint32_t* d = dst + (size_t)g * 8;
    // word w holds pair (w>>1) + (w&1)*4
    *(uint4*)(d)     = make_uint4(f16x2(u0.x, u0.y), f16x2(u2.x, u2.y),
                                  f16x2(u0.z, u0.w), f16x2(u2.z, u2.w));
    *(uint4*)(d + 4) = make_uint4(f16x2(u1.x, u1.y), f16x2(u3.x, u3.y),
                                  f16x2(u1.z, u1.w), f16x2(u3.z, u3.w));
}

// ---------------------------------------------------------------------------
// NT GEMM on pair-interleaved fp16 (fp32 accum): C[M,N] = A[M,K] * B[N,K]^T.
// CTA tile 128x128, BK=16 (one k16 group per iter = one 32B row-slice),
// 256 threads = 8 warps (4x2), warp tile 32x64.
// cp.async 4-stage pipeline of fp16; fragments are direct LDS.64, no CVT.
// smem rows stride 8 words (32B, no pad) -> provably conflict-free.
// MODE 0: plain fp32 C write.  MODE 1: fused RoPE + head split (QKV).
// ---------------------------------------------------------------------------
#define NSTAGE 4
#define STAGE_W (2 * 128 * 8)                  // A + B rows per stage (words)
#define GEMM_SMEM (NSTAGE * STAGE_W * (int)sizeof(uint32_t))   // 32768 B

template <int MODE>
__global__ __launch_bounds__(256, 2) void gemm_nt_f16(
    const uint32_t* __restrict__ A, const uint32_t* __restrict__ B,
    float* __restrict__ C, int M, int N, int K)
{
    extern __shared__ __align__(16) uint32_t gsm[];

    const int tid  = threadIdx.x;
    const int lane = tid & 31;
    const int w    = tid >> 5;
    const int lr   = lane >> 2;
    const int lc   = lane & 3;
    const int wm   = (w >> 1) * 32;
    const int wn   = (w & 1) * 64;
    const int bm   = blockIdx.y * 128;
    const int bn   = blockIdx.x * 128;

    const uint32_t sbase = smem_u32(gsm);
    const int KW = K / 2;                      // row stride in words (gmem)

    float acc[2][8][4] = {};

    const uint32_t* Abase = A + (size_t)bm * KW;
    const uint32_t* Bbase = B + (size_t)bn * KW;

    // staging: A 128 rows x 2 chunks(16B) + B same = 512 chunks, 2/thread
    auto issue_stage = [&](int it, int stage) {
        uint32_t sA = sbase + stage * STAGE_W * 4;
        uint32_t sB = sA + 128 * 8 * 4;
#pragma unroll
        for (int i = 0; i < 1; i++) {
            int id = tid;                      // 0..255 -> A chunks
            int r = id >> 1;
            int c = id & 1;
            CP_ASYNC16(sA + (r * 8 + c * 4) * 4, Abase + (size_t)r * KW + it * 8 + c * 4);
            CP_ASYNC16(sB + (r * 8 + c * 4) * 4, Bbase + (size_t)r * KW + it * 8 + c * 4);
        }
    };

    const int NIT = K / 16;
#pragma unroll
    for (int s = 0; s < NSTAGE - 1; s++) {
        issue_stage(s, s);
        CP_COMMIT();
    }

    for (int it = 0; it < NIT; it++) {
        CP_WAIT(NSTAGE - 2);
        __syncthreads();

        if (it + NSTAGE - 1 < NIT) {
            issue_stage(it + NSTAGE - 1, (it + NSTAGE - 1) % NSTAGE);
            CP_COMMIT();
        }

        const uint32_t* Ac = gsm + (it % NSTAGE) * STAGE_W;
        const uint32_t* Bc = Ac + 128 * 8;

        uint32_t a[2][4];
#pragma unroll
        for (int mt = 0; mt < 2; mt++) {
            int m = wm + mt * 16 + lr;
            uint2 u0 = *(const uint2*)&Ac[m * 8 + lc * 2];          // a0, a2
            uint2 u1 = *(const uint2*)&Ac[(m + 8) * 8 + lc * 2];    // a1, a3
            a[mt][0] = u0.x; a[mt][2] = u0.y;
            a[mt][1] = u1.x; a[mt][3] = u1.y;
        }
        uint32_t b[8][2];
#pragma unroll
        for (int nt = 0; nt < 8; nt++) {
            uint2 v = *(const uint2*)&Bc[(wn + nt * 8 + lr) * 8 + lc * 2];
            b[nt][0] = v.x; b[nt][1] = v.y;
        }
#pragma unroll
        for (int mt = 0; mt < 2; mt++)
#pragma unroll
            for (int nt = 0; nt < 8; nt++)
                MMA_F16(acc[mt][nt], a[mt][0], a[mt][1], a[mt][2], a[mt][3],
                        b[nt][0], b[nt][1]);

        __syncthreads();
    }

    // ---- epilogue ----
    if (MODE == 0) {
#pragma unroll
        for (int mt = 0; mt < 2; mt++) {
#pragma unroll
            for (int nt = 0; nt < 8; nt++) {
                size_t r = (size_t)(bm + wm + mt * 16 + lr);
                int col = bn + wn + nt * 8 + 2 * lc;
                *(float2*)&C[r * N + col] =
                    make_float2(acc[mt][nt][0], acc[mt][nt][1]);
                *(float2*)&C[(r + 8) * N + col] =
                    make_float2(acc[mt][nt][2], acc[mt][nt][3]);
            }
        }
    } else {
        // fused RoPE + head split. col pair (2lc, 2lc+1) == rope pair (j, j+1).
        // Q/K stored fp16 pair-interleaved; V stored fp32.
#pragma unroll
        for (int mt = 0; mt < 2; mt++) {
#pragma unroll
            for (int nt = 0; nt < 8; nt++) {
                int col    = bn + wn + nt * 8 + 2 * lc;
                int s      = col >> 10;              // 0=q 1=k 2=v
                int within = col & (CDIM - 1);
                int hh     = within >> 6;
                int j      = within & (DH - 1);      // even
                int pi     = j >> 1;                 // pair index 0..31
                int grp    = pi >> 3;
                int p      = pi & 7;
                int slot   = 2 * (p & 3) + (p >> 2);
#pragma unroll
                for (int h2 = 0; h2 < 2; h2++) {
                    int row = bm + wm + mt * 16 + lr + 8 * h2;
                    int t   = row & (TSEQ - 1);
                    int b_  = row >> 11;
                    float e0 = acc[mt][nt][2 * h2];
                    float e1 = acc[mt][nt][2 * h2 + 1];
                    size_t rowbase = ((size_t)(b_ * NH + hh) * TSEQ) + t;
                    if (s == 2) {
                        *(float2*)(g_Vh + rowbase * DH + j) = make_float2(e0, e1);
                    } else {
                        float c  = g_cosT[t * 32 + pi];
                        float sn = g_sinT[t * 32 + pi];
                        float o0 = e0 * c - e1 * sn;
                        float o1 = e1 * c + e0 * sn;
                        size_t wdst = rowbase * 32 + grp * 8 + slot;
                        if (s == 0) {
                            g_Qh16[wdst] = f16x2(o0 * 0.125f, o1 * 0.125f);
                        } else {
                            g_Kh16[wdst] = f16x2(o0, o1);
                        }
                    }
                }
            }
        }
    }
}

// ---------------------------------------------------------------------------
// Flash attention, fp16 mma (fp32 accum). Q tile 128 rows (8 warps x m16),
// K tile 64. Q fragments = direct uint2 gmem loads (interleaved fp16).
// K tile = raw interleaved fp16, LDG.128->STS.128, 160B rows (conflict-free).
// V = fp32 smem, packed at fragment build (R14 path, measured best).
// P = fp16 [q][144B] (R14 path). O written as interleaved fp16 to g_Oh16.
// ---------------------------------------------------------------------------
#define KROWW 40                     // K smem row stride in words (160B)
#define APV 68                       // V row stride in fp32 words
#define PSTRIDE 144                  // bytes per P row
#define ATTN_SMEM (64 * KROWW * 4 + 64 * APV * 4 + 128 * PSTRIDE)  // 46080 B

__global__ __launch_bounds__(256) void attn_f16_kernel() {
    extern __shared__ __align__(16) char sm[];
    uint32_t* KsW = (uint32_t*)sm;                       // [64 key][KROWW]
    float*    Vs  = (float*)(sm + 64 * KROWW * 4);       // [64 key][APV]
    char*     Ps16 = sm + 64 * KROWW * 4 + 64 * APV * 4; // [128 q][PSTRIDE]

    const int tid  = threadIdx.x;
    const int lane = tid & 31;
    const int w    = tid >> 5;          // warp 0..7 -> q rows w*16..w*16+15
    const int lr   = lane >> 2;
    const int lc   = lane & 3;
    const int iq   = blockIdx.x;        // q tile (128 rows)
    const int bh   = blockIdx.y;

    const uint32_t* Qw = g_Qh16 + ((size_t)bh * TSEQ + iq * 128) * 32;
    const uint32_t* Kw = g_Kh16 + (size_t)bh * TSEQ * 32;
    const float*    Vg = g_Vh   + (size_t)bh * TSEQ * DH;

    // Q fragments (already fp16-interleaved in gmem): 2 LDG.64 per k16 group
    uint32_t qf[4][4];
    {
        const uint32_t* q0 = Qw + (w * 16 + lr) * 32;
        const uint32_t* q1 = q0 + 8 * 32;
#pragma unroll
        for (int kk = 0; kk < 4; kk++) {
            uint2 u0 = *(const uint2*)&q0[kk * 8 + lc * 2];   // a0, a2
            uint2 u1 = *(const uint2*)&q1[kk * 8 + lc * 2];   // a1, a3
            qf[kk][0] = u0.x; qf[kk][2] = u0.y;
            qf[kk][1] = u1.x; qf[kk][3] = u1.y;
        }
    }

    float oacc[8][4] = {};
    float mrow[2] = {-INFINITY, -INFINITY};
    float lrow[2] = {0.f, 0.f};

    const int NJ = 2 * iq + 2;          // key tiles covering keys <= max row
    for (int j = 0; j < NJ; j++) {
        __syncthreads();                // prior tile's smem reads complete
        const uint32_t* Kt = Kw + (size_t)(j * 64) * 32;
        const float*    Vt = Vg + (size_t)(j * 64) * DH;

        // ---- stage K: raw interleaved fp16, 2 x (LDG.128 -> STS.128) ----
#pragma unroll
        for (int i = 0; i < 2; i++) {
            int id = tid + i * 256;          // 0..511
            int r = id >> 3;
            int c = id & 7;
            uint4 v = *(const uint4*)(Kt + (size_t)r * 32 + c * 4);
            *(uint4*)&KsW[r * KROWW + c * 4] = v;
        }
        // ---- stage V: raw fp32, 4 x (LDG.128 -> STS.128) ----
#pragma unroll
        for (int i = 0; i < 4; i++) {
            int id = tid + i * 256;
            int r = id >> 4;
            int c = id & 15;
            *(float4*)&Vs[r * APV + c * 4] = *(const float4*)(Vt + r * DH + c * 4);
        }
        __syncthreads();

        // ---- S = Q K^T  (m16 x n64, 4 x k16) ----
        float s[8][4] = {};
#pragma unroll
        for (int kk = 0; kk < 4; kk++) {
#pragma unroll
            for (int nt = 0; nt < 8; nt++) {
                uint2 b2 = *(const uint2*)&KsW[(nt * 8 + lr) * KROWW + kk * 8 + lc * 2];
                MMA_F16(s[nt], qf[kk][0], qf[kk][1], qf[kk][2], qf[kk][3],
                        b2.x, b2.y);
            }
        }

        // ---- causal mask (only last two tiles can be partial) ----
        if (j >= 2 * iq) {
            int rbase = iq * 128 + w * 16 + lr;
            int cbase = j * 64 + 2 * lc;
#pragma unroll
            for (int nt = 0; nt < 8; nt++) {
#pragma unroll
                for (int e = 0; e < 4; e++) {
                    int rl = rbase + (e >> 1) * 8;
                    int cl = cbase + nt * 8 + (e & 1);
                    if (cl > rl) s[nt][e] = -INFINITY;
                }
            }
        }

        // ---- online softmax (per row half) + P store (fp16) ----
#pragma unroll
        for (int h = 0; h < 2; h++) {
            float mx = -INFINITY;
#pragma unroll
            for (int nt = 0; nt < 8; nt++)
                mx = fmaxf(mx, fmaxf(s[nt][2 * h], s[nt][2 * h + 1]));
            mx = fmaxf(mx, __shfl_xor_sync(0xffffffffu, mx, 1));
            mx = fmaxf(mx, __shfl_xor_sync(0xffffffffu, mx, 2));
            float mnew = fmaxf(mrow[h], mx);
            float alpha = __expf(mrow[h] - mnew);
            float rs = 0.f;
#pragma unroll
            for (int nt = 0; nt < 8; nt++) {
                float p0 = __expf(s[nt][2 * h] - mnew);
                float p1 = __expf(s[nt][2 * h + 1] - mnew);
                s[nt][2 * h] = p0;
                s[nt][2 * h + 1] = p1;
                rs += p0 + p1;
            }
            rs += __shfl_xor_sync(0xffffffffu, rs, 1);
            rs += __shfl_xor_sync(0xffffffffu, rs, 2);
            lrow[h] = lrow[h] * alpha + rs;
            mrow[h] = mnew;
#pragma unroll
            for (int nt = 0; nt < 8; nt++) {
                oacc[nt][2 * h] *= alpha;
                oacc[nt][2 * h + 1] *= alpha;
            }
            int pr = w * 16 + lr + 8 * h;
#pragma unroll
            for (int nt = 0; nt < 8; nt++) {
                *(uint32_t*)(Ps16 + pr * PSTRIDE + (nt * 8 + 2 * lc) * 2) =
                    f16x2(s[nt][2 * h], s[nt][2 * h + 1]);
            }
        }
        __syncwarp();   // this warp's Ps rows only

        // ---- O += P * V  (m16 x n64, 4 x k16 over keys) ----
#pragma unroll
        for (int kk = 0; kk < 4; kk++) {
            int m = w * 16 + lr;
            const char* pa0 = Ps16 + m * PSTRIDE + (kk * 16 + 2 * lc) * 2;
            const char* pa1 = pa0 + 8 * PSTRIDE;
            uint32_t a0 = *(const uint32_t*)pa0;
            uint32_t a1 = *(const uint32_t*)pa1;
            uint32_t a2 = *(const uint32_t*)(pa0 + 16);
            uint32_t a3 = *(const uint32_t*)(pa1 + 16);
#pragma unroll
            for (int nt = 0; nt < 8; nt++) {
                int col = nt * 8 + lr;
                int r0 = (kk * 16 + 2 * lc) * APV + col;
                uint32_t b0 = f16x2(Vs[r0],            Vs[r0 + APV]);
                uint32_t b1 = f16x2(Vs[r0 + 8 * APV],  Vs[r0 + 9 * APV]);
                MMA_F16(oacc[nt], a0, a1, a2, a3, b0, b1);
            }
        }
    }

    // ---- epilogue: normalize, write interleaved fp16 to g_Oh16 ----
    const int bb = bh >> 4;
    const int hh = bh & 15;
#pragma unroll
    for (int h = 0; h < 2; h++) {
        float inv = 1.f / lrow[h];
        size_t row = (size_t)bb * TSEQ + (size_t)iq * 128 + w * 16 + lr + 8 * h;
        uint32_t* dst = g_Oh16 + row * (CDIM / 2) + hh * 32;
#pragma unroll
        for (int nt = 0; nt < 8; nt++) {
            int slot = 2 * lc + (nt & 1);
            dst[(nt >> 1) * 8 + slot] =
                f16x2(oacc[nt][2 * h] * inv, oacc[nt][2 * h + 1] * inv);
        }
    }
}

// ---------------------------------------------------------------------------
// Launch
// ---------------------------------------------------------------------------
extern "C" void kernel_launch(void* const* d_in, const int* in_sizes, int n_in,
                              void* d_out, int out_size)
{
    const float* x    = (const float*)d_in[0];
    const float* Wqkv = (const float*)d_in[2];
    const float* Wout = (const float*)d_in[3];
    for (int i = 0; i < n_in; i++) {
        if (in_sizes[i] == BT * CDIM)            x    = (const float*)d_in[i];
        else if (in_sizes[i] == 3 * CDIM * CDIM) Wqkv = (const float*)d_in[i];
        else if (in_sizes[i] == CDIM * CDIM)     Wout = (const float*)d_in[i];
    }
    float* out = (float*)d_out;

    void *p_x16, *p_Wqkv16, *p_Wout16, *p_Oh16;
    cudaGetSymbolAddress(&p_x16, g_x16);
    cudaGetSymbolAddress(&p_Wqkv16, g_Wqkv16);
    cudaGetSymbolAddress(&p_Wout16, g_Wout16);
    cudaGetSymbolAddress(&p_Oh16, g_Oh16);

    cudaFuncSetAttribute(attn_f16_kernel,
                         cudaFuncAttributeMaxDynamicSharedMemorySize, ATTN_SMEM);
    cudaFuncSetAttribute(gemm_nt_f16<0>,
                         cudaFuncAttributeMaxDynamicSharedMemorySize, GEMM_SMEM);
    cudaFuncSetAttribute(gemm_nt_f16<1>,
                         cudaFuncAttributeMaxDynamicSharedMemorySize, GEMM_SMEM);

    // 1. RoPE tables + fp16 interleaved conversions
    build_tables_kernel<<<(TSEQ * 32 + 255) / 256, 256>>>();
    convert_f16i_kernel<<<(BT * CDIM / 16 + 255) / 256, 256>>>(
        x, (uint32_t*)p_x16, BT * CDIM / 16);
    convert_f16i_kernel<<<(3 * CDIM * CDIM / 16 + 255) / 256, 256>>>(
        Wqkv, (uint32_t*)p_Wqkv16, 3 * CDIM * CDIM / 16);
    convert_f16i_kernel<<<(CDIM * CDIM / 16 + 255) / 256, 256>>>(
        Wout, (uint32_t*)p_Wout16, CDIM * CDIM / 16);

    // 2. QKV = x @ Wqkv^T with fused RoPE + head split (Q/K fp16i, V fp32)
    gemm_nt_f16<1><<<dim3(3 * CDIM / 128, BT / 128), 256, GEMM_SMEM>>>(
        (const uint32_t*)p_x16, (const uint32_t*)p_Wqkv16, nullptr,
        BT, 3 * CDIM, CDIM);

    // 3. Flash attention (causal, fp16 mma, 128-row Q tiles) -> g_Oh16
    attn_f16_kernel<<<dim3(TSEQ / 128, BH), 256, ATTN_SMEM>>>();

    // 4. out = attn_out @ Wout^T  (fp16i inputs, fp32 out)
    gemm_nt_f16<0><<<dim3(CDIM / 128, BT / 128), 256, GEMM_SMEM>>>(
        (const uint32_t*)p_Oh16, (const uint32_t*)p_Wout16, out,
        BT, CDIM, CDIM);
}